// round 10
// baseline (speedup 1.0000x reference)
#include <cuda_runtime.h>
#include <math.h>

// Batched EKF, three independent 2x2 filters per segment (blocks
// {0,2},{1,3},{4,5} of the 6x6 system -- exact factorization since P0,Q,R
// are diagonal, F is block-diagonal, H measures one state per block).
//
// Grid = 3*nb single-warp blocks: role = bid/nb (0=filter A, 1=filter B,
// 2=filter C), one segment per thread.  768 warps, each carrying only the
// ~26-instr diet filter step; no shared memory, no __syncthreads, no staging
// (R8 proved the memory path is not binding).  Depth-1 prefetch of the next
// 4 measurements.  Fused deterministic grid reduction (last-block pattern).

#define THREADS 32

__device__ float g_partials[2048];
__device__ int   g_count = 0;

__device__ __forceinline__ float tanh_fast(float x){ float y; asm("tanh.approx.f32 %0, %1;" : "=f"(y) : "f"(x)); return y; }
__device__ __forceinline__ float rcp_fast (float x){ float y; asm("rcp.approx.f32 %0, %1;"  : "=f"(y) : "f"(x)); return y; }
__device__ __forceinline__ float lg2_fast (float x){ float y; asm("lg2.approx.f32 %0, %1;"  : "=f"(y) : "f"(x)); return y; }

__global__ void __launch_bounds__(THREADS) ekf_kernel(
    const float* __restrict__ params,
    const float* __restrict__ cp,
    const float* __restrict__ init_state,
    const float* __restrict__ meas,
    float* __restrict__ out,
    int N, int T, int nb)
{
    const float DT    = 1.0f / 120.0f;
    const float GRAV  = 9.81f;
    const float KS    = 100.0f;
    const float WRAP  = 4.71238898038469f;   // 1.5*pi
    const float TWOPI = 6.283185307179586f;
    const float LN2   = 0.6931471805599453f;

    const float fric = fabsf(params[0]);
    const float damp = fabsf(params[1]);
    const float fg    = fric * GRAV;
    const float cF    = 1.0f - DT * damp;
    const float nDTfg = -DT * fg;
    const float DTfgk = DT * fg * KS;
    const float cA    = cF - DTfgk;           // a = cA + DTfgk*th^2
    const float cF2   = cF * cF;

    int bid  = blockIdx.x;
    int lane = threadIdx.x;
    int role = (bid < nb) ? 0 : (bid < 2 * nb) ? 1 : 2;
    int n    = (bid - role * nb) * THREADS + lane;

    float loss = 0.0f;

    if (n < N) {
        float acc_l2 = 0.0f, acc_m = 0.0f;
        const float* zr = meas + (size_t)n * T * 3 + role;   // stride-3 stream

        if (role < 2) {
            // ============ nonlinear sub-filter (A or B) ============
            const float Rc = expf(cp[role]);
            const float Qp = expf(cp[3]);
            const float Qv = expf(cp[4]);

            float x = init_state[n*6 + role];
            float v = init_state[n*6 + 2 + role];
            float p00q = 0.01f + Qp, p01 = 0.0f, p11 = 0.01f;

#define SUB(z_) do {                                                           \
            float th  = tanh_fast(KS * v);                                     \
            float xp  = fmaf(DT, v, x);                                        \
            float vp  = fmaf(cF, v, nDTfg * th);                               \
            float a   = fmaf(DTfgk, th * th, cA);                              \
            float m_  = fmaf(DT, p11, p01);                                    \
            float Pp01 = a * m_;                                               \
            float Pp00 = fmaf(DT, p01 + m_, p00q);                             \
            float Pp11 = fmaf(a * a, p11, Qv);                                 \
            float y  = (z_) - xp;                                              \
            float S  = Pp00 + Rc;                                              \
            float iS = rcp_fast(S);                                            \
            float w_ = iS * y;                                                 \
            x = fmaf(Pp00, w_, xp);                                            \
            v = fmaf(Pp01, w_, vp);                                            \
            float om = Rc * iS;                                                \
            p00q = fmaf(Pp00, om, Qp);                                         \
            p01  = Pp01 * om;                                                  \
            p11  = fmaf(-(Pp01 * iS), Pp01, Pp11);                             \
            acc_m = fmaf(y, w_, acc_m);                                        \
            sp *= S;                                                           \
        } while (0)

            if ((T & 3) == 0) {
                int G = T >> 2;
                float z0 = zr[0], z1 = zr[3], z2 = zr[6], z3 = zr[9];
                for (int g = 0; g < G; g++) {
                    float n0, n1, n2, n3;
                    if (g + 1 < G) {
                        const float* q = zr + (g + 1) * 12;
                        n0 = q[0]; n1 = q[3]; n2 = q[6]; n3 = q[9];
                    }
                    float sp = 1.0f;
                    SUB(z0); SUB(z1); SUB(z2); SUB(z3);
                    acc_l2 += lg2_fast(sp);
                    z0 = n0; z1 = n1; z2 = n2; z3 = n3;
                }
            } else {
                for (int t = 0; t < T; t++) {
                    float sp = 1.0f;
                    SUB(zr[t*3]);
                    acc_l2 += lg2_fast(sp);
                }
            }
#undef SUB
        } else {
            // ============ linear sub-filter C (theta/omega, wrap) ============
            const float R2v = expf(cp[2]);
            const float Qt  = expf(cp[5]);
            const float Qo  = expf(cp[6]);

            float xC = init_state[n*6+4], vC = init_state[n*6+5];
            float pC00q = 0.01f + Qt, pC01 = 0.0f, pC11 = 0.01f;

#define SUBC(z_) do {                                                          \
            float xp  = fmaf(DT, vC, xC);                                      \
            float vp  = cF * vC;                                               \
            float m_  = fmaf(DT, pC11, pC01);                                  \
            float Pp01 = cF * m_;                                              \
            float Pp00 = fmaf(DT, pC01 + m_, pC00q);                           \
            float Pp11 = fmaf(cF2, pC11, Qo);                                  \
            float y = (z_) - xp;                                               \
            if      (y >  WRAP) y -= TWOPI;                                    \
            else if (y < -WRAP) y += TWOPI;                                    \
            float S  = Pp00 + R2v;                                             \
            float iS = rcp_fast(S);                                            \
            float w_ = iS * y;                                                 \
            xC = fmaf(Pp00, w_, xp);                                           \
            vC = fmaf(Pp01, w_, vp);                                           \
            float om = R2v * iS;                                               \
            pC00q = fmaf(Pp00, om, Qt);                                        \
            pC01  = Pp01 * om;                                                 \
            pC11  = fmaf(-(Pp01 * iS), Pp01, Pp11);                            \
            acc_m = fmaf(y, w_, acc_m);                                        \
            sp *= S;                                                           \
        } while (0)

            if ((T & 3) == 0) {
                int G = T >> 2;
                float z0 = zr[0], z1 = zr[3], z2 = zr[6], z3 = zr[9];
                for (int g = 0; g < G; g++) {
                    float n0, n1, n2, n3;
                    if (g + 1 < G) {
                        const float* q = zr + (g + 1) * 12;
                        n0 = q[0]; n1 = q[3]; n2 = q[6]; n3 = q[9];
                    }
                    float sp = 1.0f;
                    SUBC(z0); SUBC(z1); SUBC(z2); SUBC(z3);
                    acc_l2 += lg2_fast(sp);
                    z0 = n0; z1 = n1; z2 = n2; z3 = n3;
                }
            } else {
                for (int t = 0; t < T; t++) {
                    float sp = 1.0f;
                    SUBC(zr[t*3]);
                    acc_l2 += lg2_fast(sp);
                }
            }
#undef SUBC
        }

        loss = 0.5f * fmaf(LN2, acc_l2, acc_m);
    }

    // ---- deterministic warp-tree reduction + last-block finish ----
    #pragma unroll
    for (int o = 16; o > 0; o >>= 1)
        loss += __shfl_down_sync(0xffffffffu, loss, o);

    int nbt = gridDim.x;
    int last = 0;
    if (lane == 0) {
        g_partials[bid] = loss;
        __threadfence();
        int old = atomicAdd(&g_count, 1);
        last = (old == nbt - 1);
    }
    last = __shfl_sync(0xffffffffu, last, 0);
    if (last) {
        __threadfence();
        float s = 0.0f;
        for (int j = lane; j < nbt; j += 32)
            s += g_partials[j];
        #pragma unroll
        for (int o = 16; o > 0; o >>= 1)
            s += __shfl_down_sync(0xffffffffu, s, o);
        if (lane == 0) {
            out[0] = s / (float)N;
            g_count = 0;   // reset for next graph replay
        }
    }
}

extern "C" void kernel_launch(void* const* d_in, const int* in_sizes, int n_in,
                              void* d_out, int out_size)
{
    const float* params = (const float*)d_in[0];
    const float* cp     = (const float*)d_in[1];
    const float* x0     = (const float*)d_in[2];
    const float* meas   = (const float*)d_in[3];
    float* out = (float*)d_out;

    int N = in_sizes[2] / 6;
    int T = in_sizes[3] / (N * 3);
    int nb = (N + THREADS - 1) / THREADS;

    ekf_kernel<<<3 * nb, THREADS>>>(params, cp, x0, meas, out, N, T, nb);
}

// round 11
// speedup vs baseline: 1.4963x; 1.4963x over previous
#include <cuda_runtime.h>
#include <math.h>

// Batched EKF, three independent 2x2 filters per segment.
// Structure identical to R8 (best-measured): block = 64 threads over 32
// segments; warp0 = filters A+B (ILP-2), warp1 = filter C.  ONE change:
// the smem staging loop is rewritten for high memory-level parallelism --
// 3 batches of 8 INDEPENDENT LDG.128 per thread (registers), then 8 STS.
// R8's fused LDG->STS pairs capped MLP at ~3/warp, capping the whole kernel
// at DRAM-latency * MLP ~ 480 GB/s = 13 us for the 6.3 MB stream.
// Fused deterministic grid reduction (last-block pattern).

#define SEGS 32
#define THREADS 64

__device__ float g_partials[1024];
__device__ int   g_count = 0;

__device__ __forceinline__ float tanh_fast(float x){ float y; asm("tanh.approx.f32 %0, %1;" : "=f"(y) : "f"(x)); return y; }
__device__ __forceinline__ float rcp_fast (float x){ float y; asm("rcp.approx.f32 %0, %1;"  : "=f"(y) : "f"(x)); return y; }
__device__ __forceinline__ float lg2_fast (float x){ float y; asm("lg2.approx.f32 %0, %1;"  : "=f"(y) : "f"(x)); return y; }

__global__ void __launch_bounds__(THREADS) ekf_kernel(
    const float* __restrict__ params,
    const float* __restrict__ cp,
    const float* __restrict__ init_state,
    const float* __restrict__ meas,
    float* __restrict__ out,
    int N, int T)
{
    const float DT    = 1.0f / 120.0f;
    const float GRAV  = 9.81f;
    const float KS    = 100.0f;
    const float WRAP  = 4.71238898038469f;   // 1.5*pi
    const float TWOPI = 6.283185307179586f;
    const float LN2   = 0.6931471805599453f;

    const float fric = fabsf(params[0]);
    const float damp = fabsf(params[1]);
    const float fg    = fric * GRAV;
    const float cF    = 1.0f - DT * damp;
    const float nDTfg = -DT * fg;
    const float DTfgk = DT * fg * KS;
    const float cA    = cF - DTfgk;           // a = cA + DTfgk*th^2
    const float cF2   = cF * cF;

    extern __shared__ float sm[];             // [SEGS][3T+1] padded rows
    const int ROW = 3 * T + 1;                // 193 for T=64 -> conflict-free

    int tid  = threadIdx.x;
    int w    = tid >> 5;
    int lane = tid & 31;
    int segBase = blockIdx.x * SEGS;

    // ---- high-MLP cooperative staging: batches of 8 independent LDG.128 ----
    {
        int valid = N - segBase;
        if (valid > SEGS) valid = SEGS;
        if (valid < 0) valid = 0;
        const float* gsrc = meas + (size_t)segBase * 3 * T;

        int per  = (3 * T) >> 2;              // float4s per segment row
        int tot  = valid * per;               // total float4s for this block
        bool fast = (((3 * T) & 3) == 0) && (valid == SEGS) &&
                    (tot % (THREADS * 8) == 0);
        if (fast) {
            const float4* g4 = (const float4*)gsrc;
            int nbatch = tot / (THREADS * 8); // 3 for T=64
            for (int b = 0; b < nbatch; b++) {
                float4 buf[8];
                #pragma unroll
                for (int i = 0; i < 8; i++)
                    buf[i] = g4[tid + (b * 8 + i) * THREADS];  // 8 independent loads
                #pragma unroll
                for (int i = 0; i < 8; i++) {
                    int f   = tid + (b * 8 + i) * THREADS;
                    int seg = f / per;
                    int off = (f - seg * per) << 2;
                    float* d = sm + seg * ROW + off;
                    d[0] = buf[i].x; d[1] = buf[i].y; d[2] = buf[i].z; d[3] = buf[i].w;
                }
            }
        } else if (((3 * T) & 3) == 0) {
            const float4* g4 = (const float4*)gsrc;
            for (int f = tid; f < tot; f += THREADS) {
                float4 v = g4[f];
                int seg = f / per;
                int off = (f - seg * per) << 2;
                float* d = sm + seg * ROW + off;
                d[0] = v.x; d[1] = v.y; d[2] = v.z; d[3] = v.w;
            }
        } else {
            int totf = valid * 3 * T;
            for (int f = tid; f < totf; f += THREADS) {
                int seg = f / (3 * T);
                int off = f - seg * 3 * T;
                sm[seg * ROW + off] = gsrc[f];
            }
        }
    }
    __syncthreads();

    int n = segBase + lane;
    float loss = 0.0f;

    if (w == 0) {
        // ================= A+B warp (nonlinear, ILP-2) =================
        const float R0 = expf(cp[0]);
        const float R1 = expf(cp[1]);
        const float Qp = expf(cp[3]);
        const float Qv = expf(cp[4]);

        if (n < N) {
            float xA = init_state[n*6+0], vA = init_state[n*6+2];
            float xB = init_state[n*6+1], vB = init_state[n*6+3];
            float pA00q = 0.01f + Qp, pA01 = 0.0f, pA11 = 0.01f;
            float pB00q = 0.01f + Qp, pB01 = 0.0f, pB11 = 0.01f;

            const float* zr = sm + lane * ROW;
            float acc_l2 = 0.0f, acc_m = 0.0f;

#define SUB(x_, v_, p00q_, p01_, p11_, Rc_, z_) do {                           \
            float th  = tanh_fast(KS * (v_));                                  \
            float xp  = fmaf(DT, (v_), (x_));                                  \
            float vp  = fmaf(cF, (v_), nDTfg * th);                            \
            float a   = fmaf(DTfgk, th * th, cA);                              \
            float m_  = fmaf(DT, (p11_), (p01_));                              \
            float Pp01 = a * m_;                                               \
            float Pp00 = fmaf(DT, (p01_) + m_, (p00q_));                       \
            float Pp11 = fmaf(a * a, (p11_), Qv);                              \
            float y  = (z_) - xp;                                              \
            float S  = Pp00 + (Rc_);                                           \
            float iS = rcp_fast(S);                                            \
            float w_ = iS * y;                                                 \
            x_ = fmaf(Pp00, w_, xp);                                           \
            v_ = fmaf(Pp01, w_, vp);                                           \
            float om = (Rc_) * iS;                                             \
            p00q_ = fmaf(Pp00, om, Qp);                                        \
            p01_  = Pp01 * om;                                                 \
            p11_  = fmaf(-(Pp01 * iS), Pp01, Pp11);                            \
            acc_m = fmaf(y, w_, acc_m);                                        \
            sp *= S;                                                           \
        } while (0)

#define STEP2(z0_, z1_) do {                                                   \
            SUB(xA, vA, pA00q, pA01, pA11, R0, (z0_));                         \
            SUB(xB, vB, pB00q, pB01, pB11, R1, (z1_));                         \
        } while (0)

            if ((T & 3) == 0) {
                int G = T >> 2;
                for (int g = 0; g < G; g++) {
                    const float* zb = zr + g * 12;
                    float a0 = zb[0],  b0 = zb[1];
                    float a1 = zb[3],  b1 = zb[4];
                    float a2 = zb[6],  b2 = zb[7];
                    float a3 = zb[9],  b3 = zb[10];
                    float sp = 1.0f;
                    STEP2(a0, b0);
                    STEP2(a1, b1);
                    STEP2(a2, b2);
                    STEP2(a3, b3);
                    acc_l2 += lg2_fast(sp);
                }
            } else {
                for (int t = 0; t < T; t++) {
                    float sp = 1.0f;
                    STEP2(zr[t*3+0], zr[t*3+1]);
                    acc_l2 += lg2_fast(sp);
                }
            }
#undef STEP2
#undef SUB
            loss = 0.5f * fmaf(LN2, acc_l2, acc_m);
        }
    } else {
        // ================= C warp (linear, angle wrap) =================
        const float R2v = expf(cp[2]);
        const float Qt  = expf(cp[5]);
        const float Qo  = expf(cp[6]);

        if (n < N) {
            float xC = init_state[n*6+4], vC = init_state[n*6+5];
            float pC00q = 0.01f + Qt, pC01 = 0.0f, pC11 = 0.01f;

            const float* zr = sm + lane * ROW + 2;
            float acc_l2 = 0.0f, acc_m = 0.0f;

#define SUBC(z_) do {                                                          \
            float xp  = fmaf(DT, vC, xC);                                      \
            float vp  = cF * vC;                                               \
            float m_  = fmaf(DT, pC11, pC01);                                  \
            float Pp01 = cF * m_;                                              \
            float Pp00 = fmaf(DT, pC01 + m_, pC00q);                           \
            float Pp11 = fmaf(cF2, pC11, Qo);                                  \
            float y = (z_) - xp;                                               \
            if      (y >  WRAP) y -= TWOPI;                                    \
            else if (y < -WRAP) y += TWOPI;                                    \
            float S  = Pp00 + R2v;                                             \
            float iS = rcp_fast(S);                                            \
            float w_ = iS * y;                                                 \
            xC = fmaf(Pp00, w_, xp);                                           \
            vC = fmaf(Pp01, w_, vp);                                           \
            float om = R2v * iS;                                               \
            pC00q = fmaf(Pp00, om, Qt);                                        \
            pC01  = Pp01 * om;                                                 \
            pC11  = fmaf(-(Pp01 * iS), Pp01, Pp11);                            \
            acc_m = fmaf(y, w_, acc_m);                                        \
            sp *= S;                                                           \
        } while (0)

            if ((T & 3) == 0) {
                int G = T >> 2;
                for (int g = 0; g < G; g++) {
                    const float* zb = zr + g * 12;
                    float z0 = zb[0], z1 = zb[3], z2 = zb[6], z3 = zb[9];
                    float sp = 1.0f;
                    SUBC(z0); SUBC(z1); SUBC(z2); SUBC(z3);
                    acc_l2 += lg2_fast(sp);
                }
            } else {
                for (int t = 0; t < T; t++) {
                    float sp = 1.0f;
                    SUBC(zr[t*3]);
                    acc_l2 += lg2_fast(sp);
                }
            }
#undef SUBC
            loss = 0.5f * fmaf(LN2, acc_l2, acc_m);
        }
    }

    // ---- deterministic block reduction + last-block finish ----
    __shared__ float red[2];
    #pragma unroll
    for (int o = 16; o > 0; o >>= 1)
        loss += __shfl_down_sync(0xffffffffu, loss, o);
    if (lane == 0) red[w] = loss;
    __syncthreads();

    __shared__ int s_last;
    if (tid == 0) {
        g_partials[blockIdx.x] = red[0] + red[1];
        __threadfence();
        int old = atomicAdd(&g_count, 1);
        s_last = (old == (int)gridDim.x - 1);
    }
    __syncthreads();
    if (s_last && w == 0) {
        __threadfence();
        int nb = gridDim.x;
        float acc = 0.0f;
        for (int j = lane; j < nb; j += 32)
            acc += g_partials[j];
        #pragma unroll
        for (int o = 16; o > 0; o >>= 1)
            acc += __shfl_down_sync(0xffffffffu, acc, o);
        if (lane == 0) {
            out[0] = acc / (float)N;
            g_count = 0;   // reset for next graph replay
        }
    }
}

extern "C" void kernel_launch(void* const* d_in, const int* in_sizes, int n_in,
                              void* d_out, int out_size)
{
    const float* params = (const float*)d_in[0];
    const float* cp     = (const float*)d_in[1];
    const float* x0     = (const float*)d_in[2];
    const float* meas   = (const float*)d_in[3];
    float* out = (float*)d_out;

    int N = in_sizes[2] / 6;
    int T = in_sizes[3] / (N * 3);
    int nblocks = (N + SEGS - 1) / SEGS;
    size_t smem = (size_t)SEGS * (3 * T + 1) * sizeof(float);

    ekf_kernel<<<nblocks, THREADS, smem>>>(params, cp, x0, meas, out, N, T);
}